// round 14
// baseline (speedup 1.0000x reference)
#include <cuda_runtime.h>
#include <cuda_bf16.h>
#include <cstdint>

#define HIDDEN 2048
#define HEADS  16
#define HD     128
#define NB     2
#define SEQ    2048
#define MTOT   4096
#define BK     32
#define NSTAGE (HIDDEN/BK)        // 64

// ---------------- scratch ------------------------------------------------------
__device__ __align__(128) __nv_bfloat16 g_Ah[(size_t)MTOT*HIDDEN];
__device__ __align__(128) __nv_bfloat16 g_Al[(size_t)MTOT*HIDDEN];
__device__ __align__(128) __nv_bfloat16 g_Wh[4][(size_t)HIDDEN*HIDDEN];
__device__ __align__(128) __nv_bfloat16 g_Wl[4][(size_t)HIDDEN*HIDDEN];
__device__ __align__(128) __nv_bfloat16 g_Ch[(size_t)MTOT*HIDDEN];
__device__ __align__(128) __nv_bfloat16 g_Cl[(size_t)MTOT*HIDDEN];
__device__ __align__(128) __nv_bfloat16 g_qp[(size_t)NB*HEADS*SEQ*256];  // [bh][s][hi128|lo128]
__device__ __align__(128) __nv_bfloat16 g_kp[(size_t)NB*HEADS*SEQ*256];
__device__ __align__(128) __nv_bfloat16 g_vh[(size_t)NB*HEADS*HD*SEQ];   // [bh][d][s]
__device__ __align__(128) __nv_bfloat16 g_vl[(size_t)NB*HEADS*HD*SEQ];
__device__ float g_cos[SEQ*64];
__device__ float g_sin[SEQ*64];

__device__ __forceinline__ void mma16816(float* c, const uint32_t* a, const uint32_t* b) {
    asm volatile(
        "mma.sync.aligned.m16n8k16.row.col.f32.bf16.bf16.f32 "
        "{%0,%1,%2,%3}, {%4,%5,%6,%7}, {%8,%9}, {%0,%1,%2,%3};"
        : "+f"(c[0]), "+f"(c[1]), "+f"(c[2]), "+f"(c[3])
        : "r"(a[0]), "r"(a[1]), "r"(a[2]), "r"(a[3]), "r"(b[0]), "r"(b[1]));
}
__device__ __forceinline__ void cp_async16(uint32_t saddr, const void* gaddr) {
    asm volatile("cp.async.ca.shared.global [%0], [%1], 16;" :: "r"(saddr), "l"(gaddr));
}
__device__ __forceinline__ void cp_async16cg(uint32_t saddr, const void* gaddr) {
    asm volatile("cp.async.cg.shared.global [%0], [%1], 16;" :: "r"(saddr), "l"(gaddr));
}
#define CP_COMMIT() asm volatile("cp.async.commit_group;" ::: "memory")
#define CP_WAIT(n)  asm volatile("cp.async.wait_group %0;" :: "n"(n) : "memory")
#define LDMX4(d0,d1,d2,d3,addr) \
    asm volatile("ldmatrix.sync.aligned.m8n8.x4.shared.b16 {%0,%1,%2,%3}, [%4];" \
                 : "=r"(d0), "=r"(d1), "=r"(d2), "=r"(d3) : "r"(addr))
#define PACK_BF2(dst, flo, fhi) \
    asm("cvt.rn.bf16x2.f32 %0, %1, %2;" : "=r"(dst) : "f"(fhi), "f"(flo))
__device__ __forceinline__ uint32_t smem_u32(const void* p) {
    uint32_t a;
    asm("{ .reg .u64 t; cvta.to.shared.u64 t, %1; cvt.u32.u64 %0, t; }" : "=r"(a) : "l"(p));
    return a;
}

__global__ void rope_table_kernel() {
    int idx = blockIdx.x * blockDim.x + threadIdx.x;
    if (idx >= SEQ * 64) return;
    int s = idx >> 6, i = idx & 63;
    double invf = pow(10000.0, -(double)i / 64.0);
    double ang = (double)s * invf;
    g_cos[idx] = (float)cos(ang);
    g_sin[idx] = (float)sin(ang);
}

__global__ void convert_x(const float* __restrict__ src) {
    long idx = (long)blockIdx.x * blockDim.x + threadIdx.x;
    if (idx >= (long)MTOT * (HIDDEN / 4)) return;
    float4 x = ((const float4*)src)[idx];
    __nv_bfloat16 hv[4] = {__float2bfloat16(x.x), __float2bfloat16(x.y),
                           __float2bfloat16(x.z), __float2bfloat16(x.w)};
    __nv_bfloat16 lv[4] = {__float2bfloat16(x.x - __bfloat162float(hv[0])),
                           __float2bfloat16(x.y - __bfloat162float(hv[1])),
                           __float2bfloat16(x.z - __bfloat162float(hv[2])),
                           __float2bfloat16(x.w - __bfloat162float(hv[3]))};
    ((uint2*)g_Ah)[idx] = *(uint2*)hv;
    ((uint2*)g_Al)[idx] = *(uint2*)lv;
}

__global__ void convert_w4(const float* __restrict__ w0, const float* __restrict__ w1,
                           const float* __restrict__ w2, const float* __restrict__ w3) {
    long idx = (long)blockIdx.x * blockDim.x + threadIdx.x;
    const long per = (long)HIDDEN * (HIDDEN / 4);
    if (idx >= 4 * per) return;
    int which = (int)(idx / per);
    long li = idx - (long)which * per;
    const float* src = (which == 0) ? w0 : (which == 1) ? w1 : (which == 2) ? w2 : w3;
    float4 x = ((const float4*)src)[li];
    __nv_bfloat16 hv[4] = {__float2bfloat16(x.x), __float2bfloat16(x.y),
                           __float2bfloat16(x.z), __float2bfloat16(x.w)};
    __nv_bfloat16 lv[4] = {__float2bfloat16(x.x - __bfloat162float(hv[0])),
                           __float2bfloat16(x.y - __bfloat162float(hv[1])),
                           __float2bfloat16(x.z - __bfloat162float(hv[2])),
                           __float2bfloat16(x.w - __bfloat162float(hv[3]))};
    ((uint2*)g_Wh[which])[li] = *(uint2*)hv;
    ((uint2*)g_Wl[which])[li] = *(uint2*)lv;
}

// ------- GEMM: D = Ah*Wh^T + Ah*Wl^T + Al*Wh^T -------------------------------
// 128 threads (4 warps, 2x2), warp tile 64x64, BK=32, double-buffer + double-sync.
#define TS    80
#define TSZ   (128*TS)
#define G_SMEM_BYTES (8*TSZ)          // 81920/CTA; 2 CTAs/SM

__global__ __launch_bounds__(128, 2)
void gemm3(const __nv_bfloat16* __restrict__ Ah, const __nv_bfloat16* __restrict__ Al,
           const __nv_bfloat16* __restrict__ Wh0, const __nv_bfloat16* __restrict__ Wl0,
           float* __restrict__ Dout, int fused)
{
    extern __shared__ char smem[];
    uint32_t sb = smem_u32(smem);
    int tid = threadIdx.x, wid = tid >> 5, lane = tid & 31;
    int warpm = wid >> 1, warpn = wid & 1;    // 2x2 warp grid
    int lrw = lane >> 2, lk = lane & 3;

    int n0, mode;
    const __nv_bfloat16 *Wh, *Wl;
    if (fused) {
        int which = blockIdx.x >> 4;
        n0 = (blockIdx.x & 15) * 128;
        Wh = Wh0 + (size_t)which * HIDDEN * HIDDEN;
        Wl = Wl0 + (size_t)which * HIDDEN * HIDDEN;
        mode = which;
    } else { n0 = blockIdx.x * 128; Wh = Wh0; Wl = Wl0; mode = 3; }
    int m0 = blockIdx.y * 128;

    float acc[4][8][4];
    #pragma unroll
    for (int i = 0; i < 4; i++)
        #pragma unroll
        for (int j = 0; j < 8; j++)
            #pragma unroll
            for (int r = 0; r < 4; r++) acc[i][j][r] = 0.f;

    // stage loader: 4 tiles x 128 rows x 64B; one row per thread per tile
    const char* g0[4] = {
        (const char*)(Ah + (size_t)(m0 + tid) * HIDDEN),
        (const char*)(Al + (size_t)(m0 + tid) * HIDDEN),
        (const char*)(Wh + (size_t)(n0 + tid) * HIDDEN),
        (const char*)(Wl + (size_t)(n0 + tid) * HIDDEN) };
    auto issue_stage = [&](int kelem, int buf) {
        #pragma unroll
        for (int t = 0; t < 4; t++) {
            uint32_t s = sb + (buf * 4 + t) * TSZ + tid * TS;
            const char* g = g0[t] + (size_t)kelem * 2;
            #pragma unroll
            for (int j = 0; j < 4; j++) cp_async16(s + j * 16, g + j * 16);
        }
        CP_COMMIT();
    };

    uint32_t aOff = (uint32_t)((warpm * 64 + (lane & 15)) * TS + ((lane >> 4) << 4));
    uint32_t bOff = (uint32_t)(((lane & 7) + ((lane >> 4) << 3)) * TS + (((lane >> 3) & 1) << 4));

    issue_stage(0, 0);
    for (int st = 0; st < NSTAGE; st++) {
        if (st + 1 < NSTAGE) { issue_stage((st + 1) * BK, (st + 1) & 1); CP_WAIT(1); }
        else                 { CP_WAIT(0); }
        __syncthreads();

        uint32_t base = sb + (st & 1) * 4 * TSZ;
        #pragma unroll
        for (int s = 0; s < 2; s++) {
            uint32_t ah[4][4], al[4][4];
            #pragma unroll
            for (int i = 0; i < 4; i++) {
                LDMX4(ah[i][0], ah[i][1], ah[i][2], ah[i][3],
                      base + aOff + i * 16 * TS + s * 32);
                LDMX4(al[i][0], al[i][1], al[i][2], al[i][3],
                      base + TSZ + aOff + i * 16 * TS + s * 32);
            }
            #pragma unroll
            for (int p = 0; p < 4; p++) {
                uint32_t nb = bOff + (warpn * 64 + p * 16) * TS + s * 32;
                uint32_t h0, h1, h2, h3, l0, l1, l2, l3;
                LDMX4(h0, h1, h2, h3, base + 2 * TSZ + nb);
                LDMX4(l0, l1, l2, l3, base + 3 * TSZ + nb);
                uint32_t bh0[2] = {h0, h1}, bh1[2] = {h2, h3};
                uint32_t bl0[2] = {l0, l1}, bl1[2] = {l2, l3};
                #pragma unroll
                for (int i = 0; i < 4; i++) {
                    mma16816(acc[i][2*p],   ah[i], bh0);
                    mma16816(acc[i][2*p+1], ah[i], bh1);
                    mma16816(acc[i][2*p],   ah[i], bl0);
                    mma16816(acc[i][2*p+1], ah[i], bl1);
                    mma16816(acc[i][2*p],   al[i], bh0);
                    mma16816(acc[i][2*p+1], al[i], bh1);
                }
            }
        }
        __syncthreads();
    }

    // ---- epilogue: regs -> Osm [128][132] ----
    float* Osm = (float*)smem;
    #pragma unroll
    for (int i = 0; i < 4; i++) {
        int r0 = warpm * 64 + i * 16 + lrw;
        #pragma unroll
        for (int j = 0; j < 8; j++) {
            int c0 = warpn * 64 + j * 8 + lk * 2;
            Osm[r0 * 132 + c0]           = acc[i][j][0];
            Osm[r0 * 132 + c0 + 1]       = acc[i][j][1];
            Osm[(r0 + 8) * 132 + c0]     = acc[i][j][2];
            Osm[(r0 + 8) * 132 + c0 + 1] = acc[i][j][3];
        }
    }
    __syncthreads();

    if (mode == 3) {
        #pragma unroll
        for (int it = 0; it < 32; it++) {
            int f = it * 128 + tid;
            int r = f >> 5, c4 = (f & 31) << 2;
            float4 v = *(float4*)&Osm[r * 132 + c4];
            *(float4*)&Dout[(size_t)(m0 + r) * HIDDEN + n0 + c4] = v;
        }
    } else if (mode <= 1) {
        int h = (n0 >> 7) & 15;
        const float scale = (mode == 0) ? 0.08838834764831845f : 1.0f;
        __nv_bfloat16* dst = (mode == 0) ? g_qp : g_kp;
        #pragma unroll
        for (int it = 0; it < 64; it++) {
            int f = it * 128 + tid;
            int r = f >> 6, i = f & 63;
            int m = m0 + r;
            int b = m >> 11, s = m & (SEQ - 1);
            float x1 = Osm[r * 132 + i], x2 = Osm[r * 132 + i + 64];
            float c = g_cos[s * 64 + i], sn = g_sin[s * 64 + i];
            float o1 = (x1 * c - x2 * sn) * scale;
            float o2 = (x2 * c + x1 * sn) * scale;
            __nv_bfloat16 h1 = __float2bfloat16(o1), h2 = __float2bfloat16(o2);
            __nv_bfloat16 l1 = __float2bfloat16(o1 - __bfloat162float(h1));
            __nv_bfloat16 l2 = __float2bfloat16(o2 - __bfloat162float(h2));
            size_t base = ((size_t)(b * HEADS + h) * SEQ + s) * 256;
            dst[base + i] = h1; dst[base + i + 64] = h2;
            dst[base + 128 + i] = l1; dst[base + 128 + i + 64] = l2;
        }
    } else {
        int h = (n0 >> 7) & 15;
        #pragma unroll
        for (int it = 0; it < 128; it++) {
            int f = it * 128 + tid;
            int mloc = f & 127, d = (f >> 7) & 127;
            float val = Osm[mloc * 132 + d];
            int m = m0 + mloc;
            int b = m >> 11, s = m & (SEQ - 1);
            __nv_bfloat16 hv = __float2bfloat16(val);
            __nv_bfloat16 lv = __float2bfloat16(val - __bfloat162float(hv));
            size_t o = ((size_t)((b * HEADS + h) * HD + d)) * SEQ + s;
            g_vh[o] = hv; g_vl[o] = lv;
        }
    }
}

// ------------- tensor-core flash attention (R13/R10 proven) --------------------
#define AQ_STR 528
#define AK_STR 528
#define AV_STR 272
#define AOFF_K (128*AQ_STR)
#define AK_SZ  (64*AK_STR)
#define AOFF_V (AOFF_K + 2*AK_SZ)
#define AV_SZ  (128*AV_STR)
#define ATTN_SMEM (AOFF_V + 2*AV_SZ)
#define NEGB   -1e30f

__global__ __launch_bounds__(256, 1)
void attn_kernel()
{
    extern __shared__ char sm[];
    uint32_t sb = smem_u32(sm);
    int tid = threadIdx.x, wid = tid >> 5, lane = tid & 31;
    int lrw = lane >> 2, lk = lane & 3;
    int qt = 15 - (blockIdx.x >> 5);     // heavy-first
    int bh = blockIdx.x & 31;

    {
        int r = tid >> 1, c0 = (tid & 1) * 256;
        uint32_t s = sb + r * AQ_STR + c0;
        const char* g = (const char*)g_qp + ((size_t)bh * SEQ + (size_t)qt * 128 + r) * 512 + c0;
        #pragma unroll
        for (int j = 0; j < 16; j++) cp_async16cg(s + j * 16, g + j * 16);
        CP_COMMIT();
    }
    int kr = tid >> 2, kc = (tid & 3) * 128;
    int vr = tid >> 1, vh = tid & 1;
    auto issue_kv = [&](int kt, int buf) {
        uint32_t s = sb + AOFF_K + buf * AK_SZ + kr * AK_STR + kc;
        const char* g = (const char*)g_kp + ((size_t)bh * SEQ + (size_t)kt * 64 + kr) * 512 + kc;
        #pragma unroll
        for (int j = 0; j < 8; j++) cp_async16cg(s + j * 16, g + j * 16);
        uint32_t sv = sb + AOFF_V + buf * AV_SZ + vr * AV_STR + vh * 128;
        const __nv_bfloat16* vg = (vh ? g_vl : g_vh) + ((size_t)bh * HD + vr) * SEQ + (size_t)kt * 64;
        #pragma unroll
        for (int j = 0; j < 8; j++) cp_async16cg(sv + j * 16, (const char*)vg + j * 16);
        CP_COMMIT();
    };

    issue_kv(0, 0);

    float accO[16][4];
    #pragma unroll
    for (int nt = 0; nt < 16; nt++)
        #pragma unroll
        for (int r = 0; r < 4; r++) accO[nt][r] = 0.f;
    float mA = NEGB, mB = NEGB, lA = 0.f, lB = 0.f;

    uint32_t qfb = sb + (wid * 16 + (lane & 15)) * AQ_STR + ((lane >> 4) << 4);
    uint32_t kfo = (uint32_t)(((lane & 7) + ((lane >> 4) << 3)) * AK_STR + (((lane >> 3) & 1) << 4));
    uint32_t vfo = (uint32_t)(((lane & 7) + ((lane >> 4) << 3)) * AV_STR + (((lane >> 3) & 1) << 4));
    int rgA = qt * 128 + wid * 16 + lrw;
    int nkt = 2 * qt + 2;

    CP_WAIT(1);
    __syncthreads();
    uint32_t qhi[8][4], qlo[8][4];
    #pragma unroll
    for (int ks = 0; ks < 8; ks++) {
        LDMX4(qhi[ks][0], qhi[ks][1], qhi[ks][2], qhi[ks][3], qfb + ks * 32);
        LDMX4(qlo[ks][0], qlo[ks][1], qlo[ks][2], qlo[ks][3], qfb + 256 + ks * 32);
    }

    for (int kt = 0; kt < nkt; kt++) {
        if (kt + 1 < nkt) { issue_kv(kt + 1, (kt + 1) & 1); CP_WAIT(1); }
        else              { CP_WAIT(0); }
        __syncthreads();

        if (kt * 64 <= qt * 128 + wid * 16 + 15) {
            float sacc[8][4];
            #pragma unroll
            for (int nt = 0; nt < 8; nt++)
                #pragma unroll
                for (int r = 0; r < 4; r++) sacc[nt][r] = 0.f;

            uint32_t kbuf = sb + AOFF_K + (kt & 1) * AK_SZ + kfo;
            #pragma unroll
            for (int ks = 0; ks < 8; ks++) {
                #pragma unroll
                for (int np = 0; np < 4; np++) {
                    uint32_t base = kbuf + np * 16 * AK_STR + ks * 32;
                    uint32_t h0, h1, h2, h3, l0, l1, l2, l3;
                    LDMX4(h0, h1, h2, h3, base);
                    LDMX4(l0, l1, l2, l3, base + 256);
                    uint32_t kh0[2] = {h0, h1}, kh1[2] = {h2, h3};
                    uint32_t kl0[2] = {l0, l1}, kl1[2] = {l2, l3};
                    mma16816(sacc[2*np],   qhi[ks], kh0);
                    mma16816(sacc[2*np+1], qhi[ks], kh1);
                    mma16816(sacc[2*np],   qlo[ks], kh0);
                    mma16816(sacc[2*np+1], qlo[ks], kh1);
                    mma16816(sacc[2*np],   qhi[ks], kl0);
                    mma16816(sacc[2*np+1], qhi[ks], kl1);
                }
            }
            if (kt * 64 + 63 > qt * 128 + wid * 16) {
                #pragma unroll
                for (int nt = 0; nt < 8; nt++) {
                    int cg = kt * 64 + nt * 8 + 2 * lk;
                    if (cg     > rgA)     sacc[nt][0] = NEGB;
                    if (cg + 1 > rgA)     sacc[nt][1] = NEGB;
                    if (cg     > rgA + 8) sacc[nt][2] = NEGB;
                    if (cg + 1 > rgA + 8) sacc[nt][3] = NEGB;
                }
            }
            float nmA = mA, nmB = mB;
            #pragma unroll
            for (int nt = 0; nt < 8; nt++) {
                nmA = fmaxf(nmA, fmaxf(sacc[nt][0], sacc[nt][1]));
                nmB = fmaxf(nmB, fmaxf(sacc[nt][2], sacc[nt][3]));
            }
            nmA = fmaxf(nmA, __shfl_xor_sync(~0u, nmA, 1));
            nmA = fmaxf(nmA, __shfl_xor_sync(~0u, nmA, 2));
            nmB = fmaxf(nmB, __shfl_xor_sync(~0u, nmB, 1));
            nmB = fmaxf(nmB, __shfl_xor_sync(~0u, nmB, 2));
            float coA = __expf(mA - nmA), coB = __expf(mB - nmB);
            mA = nmA; mB = nmB;
            float sumA = 0.f, sumB = 0.f;
            #pragma unroll
            for (int nt = 0; nt < 8; nt++) {
                sacc[nt][0] = __expf(sacc[nt][0] - nmA);
                sacc[nt][1] = __expf(sacc[nt][1] - nmA);
                sacc[nt][2] = __expf(sacc[nt][2] - nmB);
                sacc[nt][3] = __expf(sacc[nt][3] - nmB);
                sumA += sacc[nt][0] + sacc[nt][1];
                sumB += sacc[nt][2] + sacc[nt][3];
            }
            sumA += __shfl_xor_sync(~0u, sumA, 1);
            sumA += __shfl_xor_sync(~0u, sumA, 2);
            sumB += __shfl_xor_sync(~0u, sumB, 1);
            sumB += __shfl_xor_sync(~0u, sumB, 2);
            lA = lA * coA + sumA;
            lB = lB * coB + sumB;
            #pragma unroll
            for (int nt = 0; nt < 16; nt++) {
                accO[nt][0] *= coA; accO[nt][1] *= coA;
                accO[nt][2] *= coB; accO[nt][3] *= coB;
            }
            uint32_t phi[4][4], plo[4][4];
            #pragma unroll
            for (int s = 0; s < 4; s++) {
                #pragma unroll
                for (int half = 0; half < 2; half++) {
                    int nt = 2 * s + half;
                    float p0 = sacc[nt][0], p1 = sacc[nt][1];
                    float p2 = sacc[nt][2], p3 = sacc[nt][3];
                    PACK_BF2(phi[s][2*half],   p0, p1);
                    PACK_BF2(phi[s][2*half+1], p2, p3);
                    float r0 = p0 - __bfloat162float(__float2bfloat16(p0));
                    float r1 = p1 - __bfloat162float(__float2bfloat16(p1));
                    float r2 = p2 - __bfloat162float(__float2bfloat16(p2));
                    float r3 = p3 - __bfloat162float(__float2bfloat16(p3));
                    PACK_BF2(plo[s][2*half],   r0, r1);
                    PACK_BF2(plo[s][2*half+1], r2, r3);
                }
            }
            uint32_t vbuf = sb + AOFF_V + (kt & 1) * AV_SZ + vfo;
            #pragma unroll
            for (int ks = 0; ks < 4; ks++) {
                #pragma unroll
                for (int nt16 = 0; nt16 < 8; nt16++) {
                    uint32_t base = vbuf + nt16 * 16 * AV_STR + ks * 32;
                    uint32_t h0, h1, h2, h3, l0, l1, l2, l3;
                    LDMX4(h0, h1, h2, h3, base);
                    LDMX4(l0, l1, l2, l3, base + 128);
                    uint32_t vh0[2] = {h0, h1}, vh1[2] = {h2, h3};
                    uint32_t vl0[2] = {l0, l1}, vl1[2] = {l2, l3};
                    mma16816(accO[2*nt16],   phi[ks], vh0);
                    mma16816(accO[2*nt16+1], phi[ks], vh1);
                    mma16816(accO[2*nt16],   plo[ks], vh0);
                    mma16816(accO[2*nt16+1], plo[ks], vh1);
                    mma16816(accO[2*nt16],   phi[ks], vl0);
                    mma16816(accO[2*nt16+1], phi[ks], vl1);
                }
            }
        }
        __syncthreads();
    }

    float iA = 1.f / lA, iB = 1.f / lB;
    float* Osm = (float*)sm;
    int r0 = wid * 16 + lrw;
    #pragma unroll
    for (int nt = 0; nt < 16; nt++) {
        int c = nt * 8 + 2 * lk;
        *(float2*)&Osm[r0 * 132 + c]       = make_float2(accO[nt][0] * iA, accO[nt][1] * iA);
        *(float2*)&Osm[(r0 + 8) * 132 + c] = make_float2(accO[nt][2] * iB, accO[nt][3] * iB);
    }
    __syncthreads();
    int bb = bh >> 4, h = bh & 15;
    #pragma unroll
    for (int it = 0; it < 32; it++) {
        int f = it * 256 + tid;
        int r = f >> 6, d2 = (f & 63) * 2;
        float v0 = Osm[r * 132 + d2], v1 = Osm[r * 132 + d2 + 1];
        __nv_bfloat16 hb[2] = {__float2bfloat16(v0), __float2bfloat16(v1)};
        __nv_bfloat16 lb[2] = {__float2bfloat16(v0 - __bfloat162float(hb[0])),
                               __float2bfloat16(v1 - __bfloat162float(hb[1]))};
        size_t row = (size_t)bb * SEQ + (size_t)qt * 128 + r;
        size_t off = row * HIDDEN + h * 128 + d2;
        *(uint32_t*)(g_Ch + off) = *(uint32_t*)hb;
        *(uint32_t*)(g_Cl + off) = *(uint32_t*)lb;
    }
}

// ------------- launcher ---------------------------------------------------------
extern "C" void kernel_launch(void* const* d_in, const int* in_sizes, int n_in,
                              void* d_out, int out_size)
{
    (void)in_sizes; (void)n_in; (void)out_size;
    const float* X  = (const float*)d_in[0];
    const float* wq = (const float*)d_in[1];
    const float* wk = (const float*)d_in[2];
    const float* wv = (const float*)d_in[3];
    const float* wo = (const float*)d_in[4];
    float* out = (float*)d_out;

    __nv_bfloat16 *ah, *al, *wh, *wl, *ch, *cl;
    cudaGetSymbolAddress((void**)&ah, g_Ah);
    cudaGetSymbolAddress((void**)&al, g_Al);
    cudaGetSymbolAddress((void**)&wh, g_Wh);
    cudaGetSymbolAddress((void**)&wl, g_Wl);
    cudaGetSymbolAddress((void**)&ch, g_Ch);
    cudaGetSymbolAddress((void**)&cl, g_Cl);

    cudaFuncSetAttribute(gemm3, cudaFuncAttributeMaxDynamicSharedMemorySize, G_SMEM_BYTES);
    cudaFuncSetAttribute(attn_kernel, cudaFuncAttributeMaxDynamicSharedMemorySize, ATTN_SMEM);

    rope_table_kernel<<<(SEQ * 64 + 255) / 256, 256>>>();

    convert_x<<<(MTOT * HIDDEN / 4 + 255) / 256, 256>>>(X);
    convert_w4<<<(4 * HIDDEN * (HIDDEN / 4) + 255) / 256, 256>>>(wq, wk, wv, wo);

    gemm3<<<dim3(48, 32), 128, G_SMEM_BYTES>>>(ah, al, wh, wl, out, 1);

    attn_kernel<<<512, 256, ATTN_SMEM>>>();

    gemm3<<<dim3(16, 32), 128, G_SMEM_BYTES>>>(
        ch, cl,
        wh + (size_t)3 * HIDDEN * HIDDEN, wl + (size_t)3 * HIDDEN * HIDDEN,
        out, 0);
}

// round 15
// speedup vs baseline: 1.3128x; 1.3128x over previous
#include <cuda_runtime.h>
#include <cuda_bf16.h>
#include <cuda_fp16.h>
#include <cstdint>

#define HIDDEN 2048
#define HEADS  16
#define HD     128
#define NB     2
#define SEQ    2048
#define MTOT   4096
#define BK     32
#define NSTAGE (HIDDEN/BK)        // 64

// ---------------- scratch ------------------------------------------------------
__device__ __align__(128) __nv_bfloat16 g_Ah[(size_t)MTOT*HIDDEN];    // X bf16 hi
__device__ __align__(128) __nv_bfloat16 g_Al[(size_t)MTOT*HIDDEN];    // X bf16 lo
__device__ __align__(128) __half        g_Afh[(size_t)MTOT*HIDDEN];   // X fp16 hi
__device__ __align__(128) __half        g_Afl[(size_t)MTOT*HIDDEN];   // X fp16 lo
__device__ __align__(128) __nv_bfloat16 g_Wbh[2][(size_t)HIDDEN*HIDDEN]; // wq,wk hi
__device__ __align__(128) __nv_bfloat16 g_Wbl[2][(size_t)HIDDEN*HIDDEN]; // wq,wk lo
__device__ __align__(128) __half        g_Wvf[(size_t)HIDDEN*HIDDEN];    // wv fp16
__device__ __align__(128) __half        g_Wof[(size_t)HIDDEN*HIDDEN];    // wo fp16
__device__ __align__(128) __half        g_Ch[(size_t)MTOT*HIDDEN];    // ctx fp16 hi
__device__ __align__(128) __half        g_Cl[(size_t)MTOT*HIDDEN];    // ctx fp16 lo
__device__ __align__(128) __nv_bfloat16 g_qp[(size_t)NB*HEADS*SEQ*256];  // [bh][s][hi128|lo128]
__device__ __align__(128) __nv_bfloat16 g_kp[(size_t)NB*HEADS*SEQ*256];
__device__ __align__(128) __half        g_vfh[(size_t)NB*HEADS*HD*SEQ];  // [bh][d][s] fp16
__device__ __align__(128) __half        g_vfl[(size_t)NB*HEADS*HD*SEQ];
__device__ float g_cos[SEQ*64];
__device__ float g_sin[SEQ*64];

// ---------------- helpers ------------------------------------------------------
__device__ __forceinline__ void mma16816b(float* c, const uint32_t* a, const uint32_t* b) {
    asm volatile(
        "mma.sync.aligned.m16n8k16.row.col.f32.bf16.bf16.f32 "
        "{%0,%1,%2,%3}, {%4,%5,%6,%7}, {%8,%9}, {%0,%1,%2,%3};"
        : "+f"(c[0]), "+f"(c[1]), "+f"(c[2]), "+f"(c[3])
        : "r"(a[0]), "r"(a[1]), "r"(a[2]), "r"(a[3]), "r"(b[0]), "r"(b[1]));
}
__device__ __forceinline__ void mma16816f(float* c, const uint32_t* a, const uint32_t* b) {
    asm volatile(
        "mma.sync.aligned.m16n8k16.row.col.f32.f16.f16.f32 "
        "{%0,%1,%2,%3}, {%4,%5,%6,%7}, {%8,%9}, {%0,%1,%2,%3};"
        : "+f"(c[0]), "+f"(c[1]), "+f"(c[2]), "+f"(c[3])
        : "r"(a[0]), "r"(a[1]), "r"(a[2]), "r"(a[3]), "r"(b[0]), "r"(b[1]));
}
__device__ __forceinline__ void cp_async16(uint32_t saddr, const void* gaddr) {
    asm volatile("cp.async.ca.shared.global [%0], [%1], 16;" :: "r"(saddr), "l"(gaddr));
}
__device__ __forceinline__ void cp_async16cg(uint32_t saddr, const void* gaddr) {
    asm volatile("cp.async.cg.shared.global [%0], [%1], 16;" :: "r"(saddr), "l"(gaddr));
}
#define CP_COMMIT() asm volatile("cp.async.commit_group;" ::: "memory")
#define CP_WAIT(n)  asm volatile("cp.async.wait_group %0;" :: "n"(n) : "memory")
#define LDMX4(d0,d1,d2,d3,addr) \
    asm volatile("ldmatrix.sync.aligned.m8n8.x4.shared.b16 {%0,%1,%2,%3}, [%4];" \
                 : "=r"(d0), "=r"(d1), "=r"(d2), "=r"(d3) : "r"(addr))
#define PACK_F16(dst, flo, fhi) \
    asm("cvt.rn.f16x2.f32 %0, %1, %2;" : "=r"(dst) : "f"(fhi), "f"(flo))
__device__ __forceinline__ uint32_t smem_u32(const void* p) {
    uint32_t a;
    asm("{ .reg .u64 t; cvta.to.shared.u64 t, %1; cvt.u32.u64 %0, t; }" : "=r"(a) : "l"(p));
    return a;
}

__global__ void rope_table_kernel() {
    int idx = blockIdx.x * blockDim.x + threadIdx.x;
    if (idx >= SEQ * 64) return;
    int s = idx >> 6, i = idx & 63;
    double invf = pow(10000.0, -(double)i / 64.0);
    double ang = (double)s * invf;
    g_cos[idx] = (float)cos(ang);
    g_sin[idx] = (float)sin(ang);
}

// X -> bf16 hi/lo (for q,k) + fp16 hi/lo (for v)
__global__ void convert_x(const float* __restrict__ src) {
    long idx = (long)blockIdx.x * blockDim.x + threadIdx.x;
    if (idx >= (long)MTOT * (HIDDEN / 4)) return;
    float4 x = ((const float4*)src)[idx];
    float v[4] = {x.x, x.y, x.z, x.w};
    __nv_bfloat16 bh[4], bl[4];
    __half fh[4], fl[4];
    #pragma unroll
    for (int i = 0; i < 4; i++) {
        bh[i] = __float2bfloat16(v[i]);
        bl[i] = __float2bfloat16(v[i] - __bfloat162float(bh[i]));
        fh[i] = __float2half_rn(v[i]);
        fl[i] = __float2half_rn(v[i] - __half2float(fh[i]));
    }
    ((uint2*)g_Ah)[idx]  = *(uint2*)bh;
    ((uint2*)g_Al)[idx]  = *(uint2*)bl;
    ((uint2*)g_Afh)[idx] = *(uint2*)fh;
    ((uint2*)g_Afl)[idx] = *(uint2*)fl;
}

// wq,wk -> bf16 hi/lo planes; wv,wo -> fp16 single plane
__global__ void convert_w4(const float* __restrict__ w0, const float* __restrict__ w1,
                           const float* __restrict__ w2, const float* __restrict__ w3) {
    long idx = (long)blockIdx.x * blockDim.x + threadIdx.x;
    const long per = (long)HIDDEN * (HIDDEN / 4);
    if (idx >= 4 * per) return;
    int which = (int)(idx / per);
    long li = idx - (long)which * per;
    const float* src = (which == 0) ? w0 : (which == 1) ? w1 : (which == 2) ? w2 : w3;
    float4 x = ((const float4*)src)[li];
    float v[4] = {x.x, x.y, x.z, x.w};
    if (which < 2) {
        __nv_bfloat16 bh[4], bl[4];
        #pragma unroll
        for (int i = 0; i < 4; i++) {
            bh[i] = __float2bfloat16(v[i]);
            bl[i] = __float2bfloat16(v[i] - __bfloat162float(bh[i]));
        }
        ((uint2*)g_Wbh[which])[li] = *(uint2*)bh;
        ((uint2*)g_Wbl[which])[li] = *(uint2*)bl;
    } else {
        __half fh[4];
        #pragma unroll
        for (int i = 0; i < 4; i++) fh[i] = __float2half_rn(v[i]);
        __half* dst = (which == 2) ? g_Wvf : g_Wof;
        ((uint2*)dst)[li] = *(uint2*)fh;
    }
}

// ------- GEMM (R13 shape: 256 thr, 2x4 warps, warp 64x32, BK=32, double-sync) --
// FP2=0: bf16 3-pass (D = Ah*Wh + Ah*Wl + Al*Wh), modes 0/1 (q/k rope epilogue)
// FP2=1: fp16 2-pass (D = Ah*W + Al*W), mode 2 (v transpose-split) / 3 (plain f32)
#define TS    80
#define TSZ   (128*TS)
#define G_SMEM_BYTES (8*TSZ)          // 81920 max (FP2=1 uses 6*TSZ); 2 CTAs/SM

template<int FP2>
__global__ __launch_bounds__(256, 2)
void gemm3(const uint16_t* __restrict__ Ah, const uint16_t* __restrict__ Al,
           const uint16_t* __restrict__ Wh0, const uint16_t* __restrict__ Wl0,
           float* __restrict__ Dout, int fused)
{
    extern __shared__ char smem[];
    uint32_t sb = smem_u32(smem);
    int tid = threadIdx.x, wid = tid >> 5, lane = tid & 31;
    int warpm = wid >> 2, warpn = wid & 3;
    int lrw = lane >> 2, lk = lane & 3;
    const int NT = FP2 ? 3 : 4;

    int n0, mode;
    const uint16_t *Wh, *Wl;
    if (FP2) {
        mode = fused;                       // 2 or 3
        n0 = blockIdx.x * 128;
        Wh = Wh0; Wl = Wl0;
    } else {
        int which = blockIdx.x >> 4;        // 0 or 1 (q/k)
        n0 = (blockIdx.x & 15) * 128;
        Wh = Wh0 + (size_t)which * HIDDEN * HIDDEN;
        Wl = Wl0 + (size_t)which * HIDDEN * HIDDEN;
        mode = which;
    }
    int m0 = blockIdx.y * 128;

    float acc[4][4][4];
    #pragma unroll
    for (int i = 0; i < 4; i++)
        #pragma unroll
        for (int j = 0; j < 4; j++)
            #pragma unroll
            for (int r = 0; r < 4; r++) acc[i][j][r] = 0.f;

    int ld_r = tid >> 1, ld_c = (tid & 1) * 32;
    const char* g0[4] = {
        (const char*)(Ah + (size_t)(m0 + ld_r) * HIDDEN),
        (const char*)(Al + (size_t)(m0 + ld_r) * HIDDEN),
        (const char*)(Wh + (size_t)(n0 + ld_r) * HIDDEN),
        (const char*)(Wl + (size_t)(n0 + ld_r) * HIDDEN) };
    auto issue_stage = [&](int kelem, int buf) {
        #pragma unroll
        for (int t = 0; t < NT; t++) {
            uint32_t s = sb + (buf * NT + t) * TSZ + ld_r * TS + ld_c;
            const char* g = g0[t] + (size_t)kelem * 2 + ld_c;
            cp_async16(s, g);
            cp_async16(s + 16, g + 16);
        }
        CP_COMMIT();
    };

    uint32_t aOff = (uint32_t)((warpm * 64 + (lane & 15)) * TS + ((lane >> 4) << 4));
    uint32_t bOff = (uint32_t)(((lane & 7) + ((lane >> 4) << 3)) * TS + (((lane >> 3) & 1) << 4));

    issue_stage(0, 0);
    for (int st = 0; st < NSTAGE; st++) {
        if (st + 1 < NSTAGE) { issue_stage((st + 1) * BK, (st + 1) & 1); CP_WAIT(1); }
        else                 { CP_WAIT(0); }
        __syncthreads();

        uint32_t base = sb + (st & 1) * NT * TSZ;
        #pragma unroll
        for (int s = 0; s < 2; s++) {
            uint32_t ah[4][4], al[4][4];
            #pragma unroll
            for (int i = 0; i < 4; i++) {
                LDMX4(ah[i][0], ah[i][1], ah[i][2], ah[i][3],
                      base + aOff + i * 16 * TS + s * 32);
                LDMX4(al[i][0], al[i][1], al[i][2], al[i][3],
                      base + TSZ + aOff + i * 16 * TS + s * 32);
            }
            #pragma unroll
            for (int p = 0; p < 2; p++) {
                uint32_t nb = bOff + (warpn * 32 + p * 16) * TS + s * 32;
                uint32_t h0, h1, h2, h3;
                LDMX4(h0, h1, h2, h3, base + 2 * TSZ + nb);
                uint32_t bh0[2] = {h0, h1}, bh1[2] = {h2, h3};
                if (FP2) {
                    #pragma unroll
                    for (int i = 0; i < 4; i++) {
                        mma16816f(acc[i][2*p],   ah[i], bh0);
                        mma16816f(acc[i][2*p+1], ah[i], bh1);
                        mma16816f(acc[i][2*p],   al[i], bh0);
                        mma16816f(acc[i][2*p+1], al[i], bh1);
                    }
                } else {
                    uint32_t l0, l1, l2, l3;
                    LDMX4(l0, l1, l2, l3, base + 3 * TSZ + nb);
                    uint32_t bl0[2] = {l0, l1}, bl1[2] = {l2, l3};
                    #pragma unroll
                    for (int i = 0; i < 4; i++) {
                        mma16816b(acc[i][2*p],   ah[i], bh0);
                        mma16816b(acc[i][2*p+1], ah[i], bh1);
                        mma16816b(acc[i][2*p],   ah[i], bl0);
                        mma16816b(acc[i][2*p+1], ah[i], bl1);
                        mma16816b(acc[i][2*p],   al[i], bh0);
                        mma16816b(acc[i][2*p+1], al[i], bh1);
                    }
                }
            }
        }
        __syncthreads();
    }

    // ---- epilogue: regs -> Osm ----
    float* Osm = (float*)smem;
    #pragma unroll
    for (int i = 0; i < 4; i++) {
        int r0 = warpm * 64 + i * 16 + lrw;
        #pragma unroll
        for (int j = 0; j < 4; j++) {
            int c0 = warpn * 32 + j * 8 + lk * 2;
            Osm[r0 * 132 + c0]           = acc[i][j][0];
            Osm[r0 * 132 + c0 + 1]       = acc[i][j][1];
            Osm[(r0 + 8) * 132 + c0]     = acc[i][j][2];
            Osm[(r0 + 8) * 132 + c0 + 1] = acc[i][j][3];
        }
    }
    __syncthreads();

    if (FP2) {
        if (mode == 3) {
            #pragma unroll
            for (int it = 0; it < 16; it++) {
                int f = it * 256 + tid;
                int r = f >> 5, c4 = (f & 31) << 2;
                float4 v = *(float4*)&Osm[r * 132 + c4];
                *(float4*)&Dout[(size_t)(m0 + r) * HIDDEN + n0 + c4] = v;
            }
        } else {
            // mode 2: v transpose-split -> fp16 planes [bh][d][s]
            int h = (n0 >> 7) & 15;
            #pragma unroll
            for (int it = 0; it < 64; it++) {
                int f = it * 256 + tid;
                int mloc = f & 127, d = (f >> 7) & 127;
                float val = Osm[mloc * 132 + d];
                int m = m0 + mloc;
                int b = m >> 11, s = m & (SEQ - 1);
                __half hv = __float2half_rn(val);
                __half lv = __float2half_rn(val - __half2float(hv));
                size_t o = ((size_t)((b * HEADS + h) * HD + d)) * SEQ + s;
                g_vfh[o] = hv; g_vfl[o] = lv;
            }
        }
    } else {
        // modes 0/1: rope (+scale for q) then bf16 hi/lo split -> g_qp/g_kp
        int h = (n0 >> 7) & 15;
        const float scale = (mode == 0) ? 0.08838834764831845f : 1.0f;
        __nv_bfloat16* dst = (mode == 0) ? g_qp : g_kp;
        #pragma unroll
        for (int it = 0; it < 32; it++) {
            int f = it * 256 + tid;
            int r = f >> 6, i = f & 63;
            int m = m0 + r;
            int b = m >> 11, s = m & (SEQ - 1);
            float x1 = Osm[r * 132 + i], x2 = Osm[r * 132 + i + 64];
            float c = g_cos[s * 64 + i], sn = g_sin[s * 64 + i];
            float o1 = (x1 * c - x2 * sn) * scale;
            float o2 = (x2 * c + x1 * sn) * scale;
            __nv_bfloat16 h1 = __float2bfloat16(o1), h2 = __float2bfloat16(o2);
            __nv_bfloat16 l1 = __float2bfloat16(o1 - __bfloat162float(h1));
            __nv_bfloat16 l2 = __float2bfloat16(o2 - __bfloat162float(h2));
            size_t base = ((size_t)(b * HEADS + h) * SEQ + s) * 256;
            dst[base + i] = h1; dst[base + i + 64] = h2;
            dst[base + 128 + i] = l1; dst[base + 128 + i + 64] = l2;
        }
    }
}

// ------------- tensor-core flash attention (S bf16 3-pass, PV fp16 3-pass) -----
#define AQ_STR 528
#define AK_STR 528
#define AV_STR 272
#define AOFF_K (128*AQ_STR)
#define AK_SZ  (64*AK_STR)
#define AOFF_V (AOFF_K + 2*AK_SZ)
#define AV_SZ  (128*AV_STR)
#define ATTN_SMEM (AOFF_V + 2*AV_SZ)
#define NEGB   -1e30f

__global__ __launch_bounds__(256, 1)
void attn_kernel()
{
    extern __shared__ char sm[];
    uint32_t sb = smem_u32(sm);
    int tid = threadIdx.x, wid = tid >> 5, lane = tid & 31;
    int lrw = lane >> 2, lk = lane & 3;
    int qt = 15 - (blockIdx.x >> 5);     // heavy-first
    int bh = blockIdx.x & 31;

    {
        int r = tid >> 1, c0 = (tid & 1) * 256;
        uint32_t s = sb + r * AQ_STR + c0;
        const char* g = (const char*)g_qp + ((size_t)bh * SEQ + (size_t)qt * 128 + r) * 512 + c0;
        #pragma unroll
        for (int j = 0; j < 16; j++) cp_async16cg(s + j * 16, g + j * 16);
        CP_COMMIT();
    }
    int kr = tid >> 2, kc = (tid & 3) * 128;
    int vr = tid >> 1, vh = tid & 1;
    auto issue_kv = [&](int kt, int buf) {
        uint32_t s = sb + AOFF_K + buf * AK_SZ + kr * AK_STR + kc;
        const char* g = (const char*)g_kp + ((size_t)bh * SEQ + (size_t)kt * 64 + kr) * 512 + kc;
        #pragma unroll
        for (int j = 0; j < 8; j++) cp_async16cg(s + j * 16, g + j * 16);
        uint32_t sv = sb + AOFF_V + buf * AV_SZ + vr * AV_STR + vh * 128;
        const __half* vg = (vh ? g_vfl : g_vfh) + ((size_t)bh * HD + vr) * SEQ + (size_t)kt * 64;
        #pragma unroll
        for (int j = 0; j < 8; j++) cp_async16cg(sv + j * 16, (const char*)vg + j * 16);
        CP_COMMIT();
    };

    issue_kv(0, 0);

    float accO[16][4];
    #pragma unroll
    for (int nt = 0; nt < 16; nt++)
        #pragma unroll
        for (int r = 0; r < 4; r++) accO[nt][r] = 0.f;
    float mA = NEGB, mB = NEGB, lA = 0.f, lB = 0.f;

    uint32_t qfb = sb + (wid * 16 + (lane & 15)) * AQ_STR + ((lane >> 4) << 4);
    uint32_t kfo = (uint32_t)(((lane & 7) + ((lane >> 4) << 3)) * AK_STR + (((lane >> 3) & 1) << 4));
    uint32_t vfo = (uint32_t)(((lane & 7) + ((lane >> 4) << 3)) * AV_STR + (((lane >> 3) & 1) << 4));
    int rgA = qt * 128 + wid * 16 + lrw;
    int nkt = 2 * qt + 2;

    CP_WAIT(1);
    __syncthreads();
    uint32_t qhi[8][4], qlo[8][4];
    #pragma unroll
    for (int ks = 0; ks < 8; ks++) {
        LDMX4(qhi[ks][0], qhi[ks][1], qhi[ks][2], qhi[ks][3], qfb + ks * 32);
        LDMX4(qlo[ks][0], qlo[ks][1], qlo[ks][2], qlo[ks][3], qfb + 256 + ks * 32);
    }

    for (int kt = 0; kt < nkt; kt++) {
        if (kt + 1 < nkt) { issue_kv(kt + 1, (kt + 1) & 1); CP_WAIT(1); }
        else              { CP_WAIT(0); }
        __syncthreads();

        if (kt * 64 <= qt * 128 + wid * 16 + 15) {
            float sacc[8][4];
            #pragma unroll
            for (int nt = 0; nt < 8; nt++)
                #pragma unroll
                for (int r = 0; r < 4; r++) sacc[nt][r] = 0.f;

            uint32_t kbuf = sb + AOFF_K + (kt & 1) * AK_SZ + kfo;
            #pragma unroll
            for (int ks = 0; ks < 8; ks++) {
                #pragma unroll
                for (int np = 0; np < 4; np++) {
                    uint32_t base = kbuf + np * 16 * AK_STR + ks * 32;
                    uint32_t h0, h1, h2, h3, l0, l1, l2, l3;
                    LDMX4(h0, h1, h2, h3, base);
                    LDMX4(l0, l1, l2, l3, base + 256);
                    uint32_t kh0[2] = {h0, h1}, kh1[2] = {h2, h3};
                    uint32_t kl0[2] = {l0, l1}, kl1[2] = {l2, l3};
                    mma16816b(sacc[2*np],   qhi[ks], kh0);
                    mma16816b(sacc[2*np+1], qhi[ks], kh1);
                    mma16816b(sacc[2*np],   qlo[ks], kh0);
                    mma16816b(sacc[2*np+1], qlo[ks], kh1);
                    mma16816b(sacc[2*np],   qhi[ks], kl0);
                    mma16816b(sacc[2*np+1], qhi[ks], kl1);
                }
            }
            if (kt * 64 + 63 > qt * 128 + wid * 16) {
                #pragma unroll
                for (int nt = 0; nt < 8; nt++) {
                    int cg = kt * 64 + nt * 8 + 2 * lk;
                    if (cg     > rgA)     sacc[nt][0] = NEGB;
                    if (cg + 1 > rgA)     sacc[nt][1] = NEGB;
                    if (cg     > rgA + 8) sacc[nt][2] = NEGB;
                    if (cg + 1 > rgA + 8) sacc[nt][3] = NEGB;
                }
            }
            float nmA = mA, nmB = mB;
            #pragma unroll
            for (int nt = 0; nt < 8; nt++) {
                nmA = fmaxf(nmA, fmaxf(sacc[nt][0], sacc[nt][1]));
                nmB = fmaxf(nmB, fmaxf(sacc[nt][2], sacc[nt][3]));
            }
            nmA = fmaxf(nmA, __shfl_xor_sync(~0u, nmA, 1));
            nmA = fmaxf(nmA, __shfl_xor_sync(~0u, nmA, 2));
            nmB = fmaxf(nmB, __shfl_xor_sync(~0u, nmB, 1));
            nmB = fmaxf(nmB, __shfl_xor_sync(~0u, nmB, 2));
            float coA = __expf(mA - nmA), coB = __expf(mB - nmB);
            mA = nmA; mB = nmB;
            float sumA = 0.f, sumB = 0.f;
            #pragma unroll
            for (int nt = 0; nt < 8; nt++) {
                sacc[nt][0] = __expf(sacc[nt][0] - nmA);
                sacc[nt][1] = __expf(sacc[nt][1] - nmA);
                sacc[nt][2] = __expf(sacc[nt][2] - nmB);
                sacc[nt][3] = __expf(sacc[nt][3] - nmB);
                sumA += sacc[nt][0] + sacc[nt][1];
                sumB += sacc[nt][2] + sacc[nt][3];
            }
            sumA += __shfl_xor_sync(~0u, sumA, 1);
            sumA += __shfl_xor_sync(~0u, sumA, 2);
            sumB += __shfl_xor_sync(~0u, sumB, 1);
            sumB += __shfl_xor_sync(~0u, sumB, 2);
            lA = lA * coA + sumA;
            lB = lB * coB + sumB;
            #pragma unroll
            for (int nt = 0; nt < 16; nt++) {
                accO[nt][0] *= coA; accO[nt][1] *= coA;
                accO[nt][2] *= coB; accO[nt][3] *= coB;
            }
            // P split into fp16 hi/lo fragments
            uint32_t phi[4][4], plo[4][4];
            #pragma unroll
            for (int s = 0; s < 4; s++) {
                #pragma unroll
                for (int half = 0; half < 2; half++) {
                    int nt = 2 * s + half;
                    float p0 = sacc[nt][0], p1 = sacc[nt][1];
                    float p2 = sacc[nt][2], p3 = sacc[nt][3];
                    PACK_F16(phi[s][2*half],   p0, p1);
                    PACK_F16(phi[s][2*half+1], p2, p3);
                    float r0 = p0 - __half2float(__float2half_rn(p0));
                    float r1 = p1 - __half2float(__float2half_rn(p1));
                    float r2 = p2 - __half2float(__float2half_rn(p2));
                    float r3 = p3 - __half2float(__float2half_rn(p3));
                    PACK_F16(plo[s][2*half],   r0, r1);
                    PACK_F16(plo[s][2*half+1], r2, r3);
                }
            }
            // PV: fp16 3-pass (Phi*Vh + Plo*Vh + Phi*Vl)
            uint32_t vbuf = sb + AOFF_V + (kt & 1) * AV_SZ + vfo;
            #pragma unroll
            for (int ks = 0; ks < 4; ks++) {
                #pragma unroll
                for (int nt16 = 0; nt16 < 8; nt16++) {
                    uint32_t base = vbuf + nt16 * 16 * AV_STR + ks * 32;
                    uint32_t h0, h1, h2, h3, l0, l1, l2, l3;
                    LDMX4(h0, h1, h2, h3, base);
                    LDMX4(l0, l1, l2, l3, base + 128);
                    uint32_t vh0[2] = {h0, h1}, vh1[2] = {h2, h3};
                    uint32_t vl0[2] = {l0, l1}, vl1[2] = {l2, l3};
                    mma16816f(accO[2*nt16],   phi[ks], vh0);
                    mma16816f(accO[2*nt16+1], phi[ks], vh1);
                    mma16816f(accO[2*nt16],   plo[ks], vh0);
                    mma16816f(accO[2*nt16+1], plo[ks], vh1);
                    mma16816f(accO[2*nt16],   phi[ks], vl0);
                    mma16816f(accO[2*nt16+1], phi[ks], vl1);
                }
            }
        }
        __syncthreads();
    }

    float iA = 1.f / lA, iB = 1.f / lB;
    float* Osm = (float*)sm;
    int r0 = wid * 16 + lrw;
    #pragma unroll
    for (int nt = 0; nt < 16; nt++) {
        int c = nt * 8 + 2 * lk;
        *(float2*)&Osm[r0 * 132 + c]       = make_float2(accO[nt][0] * iA, accO[nt][1] * iA);
        *(float2*)&Osm[(r0 + 8) * 132 + c] = make_float2(accO[nt][2] * iB, accO[nt][3] * iB);
    }
    __syncthreads();
    // ctx -> fp16 hi/lo planes
    int bb = bh >> 4, h = bh & 15;
    #pragma unroll
    for (int it = 0; it < 32; it++) {
        int f = it * 256 + tid;
        int r = f >> 6, d2 = (f & 63) * 2;
        float v0 = Osm[r * 132 + d2], v1 = Osm[r * 132 + d2 + 1];
        __half h0 = __float2half_rn(v0), h1 = __float2half_rn(v1);
        __half e0 = __float2half_rn(v0 - __half2float(h0));
        __half e1 = __float2half_rn(v1 - __half2float(h1));
        uint32_t hp = (uint32_t)__half_as_ushort(h0) | ((uint32_t)__half_as_ushort(h1) << 16);
        uint32_t lp = (uint32_t)__half_as_ushort(e0) | ((uint32_t)__half_as_ushort(e1) << 16);
        size_t row = (size_t)bb * SEQ + (size_t)qt * 128 + r;
        size_t off = row * HIDDEN + h * 128 + d2;
        *(uint32_t*)(g_Ch + off) = hp;
        *(uint32_t*)(g_Cl + off) = lp;
    }
}

// ------------- launcher ---------------------------------------------------------
extern "C" void kernel_launch(void* const* d_in, const int* in_sizes, int n_in,
                              void* d_out, int out_size)
{
    (void)in_sizes; (void)n_in; (void)out_size;
    const float* X  = (const float*)d_in[0];
    const float* wq = (const float*)d_in[1];
    const float* wk = (const float*)d_in[2];
    const float* wv = (const float*)d_in[3];
    const float* wo = (const float*)d_in[4];
    float* out = (float*)d_out;

    uint16_t *ah, *al, *afh, *afl, *wbh, *wbl, *wvf, *wof, *ch, *cl;
    cudaGetSymbolAddress((void**)&ah,  g_Ah);
    cudaGetSymbolAddress((void**)&al,  g_Al);
    cudaGetSymbolAddress((void**)&afh, g_Afh);
    cudaGetSymbolAddress((void**)&afl, g_Afl);
    cudaGetSymbolAddress((void**)&wbh, g_Wbh);
    cudaGetSymbolAddress((void**)&wbl, g_Wbl);
    cudaGetSymbolAddress((void**)&wvf, g_Wvf);
    cudaGetSymbolAddress((void**)&wof, g_Wof);
    cudaGetSymbolAddress((void**)&ch,  g_Ch);
    cudaGetSymbolAddress((void**)&cl,  g_Cl);

    cudaFuncSetAttribute(gemm3<0>, cudaFuncAttributeMaxDynamicSharedMemorySize, G_SMEM_BYTES);
    cudaFuncSetAttribute(gemm3<1>, cudaFuncAttributeMaxDynamicSharedMemorySize, G_SMEM_BYTES);
    cudaFuncSetAttribute(attn_kernel, cudaFuncAttributeMaxDynamicSharedMemorySize, ATTN_SMEM);

    rope_table_kernel<<<(SEQ * 64 + 255) / 256, 256>>>();

    convert_x<<<(MTOT * HIDDEN / 4 + 255) / 256, 256>>>(X);
    convert_w4<<<(4 * HIDDEN * (HIDDEN / 4) + 255) / 256, 256>>>(wq, wk, wv, wo);

    // q,k projections: bf16 3-pass + rope epilogue
    gemm3<0><<<dim3(32, 32), 256, G_SMEM_BYTES>>>(ah, al, wbh, wbl, out, 1);
    // v projection: fp16 2-pass, transpose-split epilogue
    gemm3<1><<<dim3(16, 32), 256, G_SMEM_BYTES>>>(afh, afl, wvf, wvf, out, 2);

    attn_kernel<<<512, 256, ATTN_SMEM>>>();

    // output projection: fp16 2-pass, plain epilogue
    gemm3<1><<<dim3(16, 32), 256, G_SMEM_BYTES>>>(ch, cl, wof, wof, out, 3);
}

// round 16
// speedup vs baseline: 1.6170x; 1.2317x over previous
#include <cuda_runtime.h>
#include <cuda_bf16.h>
#include <cuda_fp16.h>
#include <cstdint>

#define HIDDEN 2048
#define HEADS  16
#define HD     128
#define NB     2
#define SEQ    2048
#define MTOT   4096
#define BK     32
#define NSTAGE (HIDDEN/BK)        // 64

// ---------------- scratch ------------------------------------------------------
__device__ __align__(128) __half g_Afh[(size_t)MTOT*HIDDEN];   // X fp16 hi
__device__ __align__(128) __half g_Afl[(size_t)MTOT*HIDDEN];   // X fp16 lo
__device__ __align__(128) __half g_Wf[4][(size_t)HIDDEN*HIDDEN]; // wq,wk,wv,wo fp16
__device__ __align__(128) __half g_Ch[(size_t)MTOT*HIDDEN];    // ctx fp16 hi
__device__ __align__(128) __half g_Cl[(size_t)MTOT*HIDDEN];    // ctx fp16 lo
__device__ __align__(128) __half g_qp[(size_t)NB*HEADS*SEQ*256]; // [bh][s][hi128|lo128]
__device__ __align__(128) __half g_kp[(size_t)NB*HEADS*SEQ*128]; // [bh][s][128] single
__device__ __align__(128) __half g_vf[(size_t)NB*HEADS*HD*SEQ];  // [bh][d][s] single
__device__ float g_cos[SEQ*64];
__device__ float g_sin[SEQ*64];

// ---------------- helpers ------------------------------------------------------
__device__ __forceinline__ void mma16816f(float* c, const uint32_t* a, const uint32_t* b) {
    asm volatile(
        "mma.sync.aligned.m16n8k16.row.col.f32.f16.f16.f32 "
        "{%0,%1,%2,%3}, {%4,%5,%6,%7}, {%8,%9}, {%0,%1,%2,%3};"
        : "+f"(c[0]), "+f"(c[1]), "+f"(c[2]), "+f"(c[3])
        : "r"(a[0]), "r"(a[1]), "r"(a[2]), "r"(a[3]), "r"(b[0]), "r"(b[1]));
}
__device__ __forceinline__ void cp_async16(uint32_t saddr, const void* gaddr) {
    asm volatile("cp.async.ca.shared.global [%0], [%1], 16;" :: "r"(saddr), "l"(gaddr));
}
__device__ __forceinline__ void cp_async16cg(uint32_t saddr, const void* gaddr) {
    asm volatile("cp.async.cg.shared.global [%0], [%1], 16;" :: "r"(saddr), "l"(gaddr));
}
#define CP_COMMIT() asm volatile("cp.async.commit_group;" ::: "memory")
#define CP_WAIT(n)  asm volatile("cp.async.wait_group %0;" :: "n"(n) : "memory")
#define LDMX4(d0,d1,d2,d3,addr) \
    asm volatile("ldmatrix.sync.aligned.m8n8.x4.shared.b16 {%0,%1,%2,%3}, [%4];" \
                 : "=r"(d0), "=r"(d1), "=r"(d2), "=r"(d3) : "r"(addr))
#define PACK_F16(dst, flo, fhi) \
    asm("cvt.rn.f16x2.f32 %0, %1, %2;" : "=r"(dst) : "f"(fhi), "f"(flo))
__device__ __forceinline__ uint32_t smem_u32(const void* p) {
    uint32_t a;
    asm("{ .reg .u64 t; cvta.to.shared.u64 t, %1; cvt.u32.u64 %0, t; }" : "=r"(a) : "l"(p));
    return a;
}

__global__ void rope_table_kernel() {
    int idx = blockIdx.x * blockDim.x + threadIdx.x;
    if (idx >= SEQ * 64) return;
    int s = idx >> 6, i = idx & 63;
    double invf = pow(10000.0, -(double)i / 64.0);
    double ang = (double)s * invf;
    g_cos[idx] = (float)cos(ang);
    g_sin[idx] = (float)sin(ang);
}

__global__ void convert_x(const float* __restrict__ src) {
    long idx = (long)blockIdx.x * blockDim.x + threadIdx.x;
    if (idx >= (long)MTOT * (HIDDEN / 4)) return;
    float4 x = ((const float4*)src)[idx];
    float v[4] = {x.x, x.y, x.z, x.w};
    __half fh[4], fl[4];
    #pragma unroll
    for (int i = 0; i < 4; i++) {
        fh[i] = __float2half_rn(v[i]);
        fl[i] = __float2half_rn(v[i] - __half2float(fh[i]));
    }
    ((uint2*)g_Afh)[idx] = *(uint2*)fh;
    ((uint2*)g_Afl)[idx] = *(uint2*)fl;
}

__global__ void convert_w4(const float* __restrict__ w0, const float* __restrict__ w1,
                           const float* __restrict__ w2, const float* __restrict__ w3) {
    long idx = (long)blockIdx.x * blockDim.x + threadIdx.x;
    const long per = (long)HIDDEN * (HIDDEN / 4);
    if (idx >= 4 * per) return;
    int which = (int)(idx / per);
    long li = idx - (long)which * per;
    const float* src = (which == 0) ? w0 : (which == 1) ? w1 : (which == 2) ? w2 : w3;
    float4 x = ((const float4*)src)[li];
    __half fh[4] = {__float2half_rn(x.x), __float2half_rn(x.y),
                    __float2half_rn(x.z), __float2half_rn(x.w)};
    ((uint2*)g_Wf[which])[li] = *(uint2*)fh;
}

// ------- GEMM: D = (Ah+Al) * W^T, fp16 2-pass (R13 shape, 3 tiles/stage) -------
// fused=1: grid.x=48, which=x>>4 -> mode 0(q)/1(k)/2(v). fused=0: mode 3 (wo).
#define TS    80
#define TSZ   (128*TS)
#define G_SMEM_BYTES 67584            // >= 6*TSZ (61440) and Osm (128*132*4)

__global__ __launch_bounds__(256, 2)
void gemmf(const __half* __restrict__ Ah, const __half* __restrict__ Al,
           const __half* __restrict__ W0, float* __restrict__ Dout, int fused)
{
    extern __shared__ char smem[];
    uint32_t sb = smem_u32(smem);
    int tid = threadIdx.x, wid = tid >> 5, lane = tid & 31;
    int warpm = wid >> 2, warpn = wid & 3;
    int lrw = lane >> 2, lk = lane & 3;

    int n0, mode;
    const __half* W;
    if (fused) {
        int which = blockIdx.x >> 4;       // 0,1,2
        n0 = (blockIdx.x & 15) * 128;
        W = W0 + (size_t)which * HIDDEN * HIDDEN;
        mode = which;
    } else { n0 = blockIdx.x * 128; W = W0; mode = 3; }
    int m0 = blockIdx.y * 128;

    float acc[4][4][4];
    #pragma unroll
    for (int i = 0; i < 4; i++)
        #pragma unroll
        for (int j = 0; j < 4; j++)
            #pragma unroll
            for (int r = 0; r < 4; r++) acc[i][j][r] = 0.f;

    int ld_r = tid >> 1, ld_c = (tid & 1) * 32;
    const char* g0[3] = {
        (const char*)(Ah + (size_t)(m0 + ld_r) * HIDDEN),
        (const char*)(Al + (size_t)(m0 + ld_r) * HIDDEN),
        (const char*)(W  + (size_t)(n0 + ld_r) * HIDDEN) };
    auto issue_stage = [&](int kelem, int buf) {
        #pragma unroll
        for (int t = 0; t < 3; t++) {
            uint32_t s = sb + (buf * 3 + t) * TSZ + ld_r * TS + ld_c;
            const char* g = g0[t] + (size_t)kelem * 2 + ld_c;
            cp_async16(s, g);
            cp_async16(s + 16, g + 16);
        }
        CP_COMMIT();
    };

    uint32_t aOff = (uint32_t)((warpm * 64 + (lane & 15)) * TS + ((lane >> 4) << 4));
    uint32_t bOff = (uint32_t)(((lane & 7) + ((lane >> 4) << 3)) * TS + (((lane >> 3) & 1) << 4));

    issue_stage(0, 0);
    for (int st = 0; st < NSTAGE; st++) {
        if (st + 1 < NSTAGE) { issue_stage((st + 1) * BK, (st + 1) & 1); CP_WAIT(1); }
        else                 { CP_WAIT(0); }
        __syncthreads();

        uint32_t base = sb + (st & 1) * 3 * TSZ;
        #pragma unroll
        for (int s = 0; s < 2; s++) {
            uint32_t ah[4][4], al[4][4];
            #pragma unroll
            for (int i = 0; i < 4; i++) {
                LDMX4(ah[i][0], ah[i][1], ah[i][2], ah[i][3],
                      base + aOff + i * 16 * TS + s * 32);
                LDMX4(al[i][0], al[i][1], al[i][2], al[i][3],
                      base + TSZ + aOff + i * 16 * TS + s * 32);
            }
            #pragma unroll
            for (int p = 0; p < 2; p++) {
                uint32_t nb = bOff + (warpn * 32 + p * 16) * TS + s * 32;
                uint32_t h0, h1, h2, h3;
                LDMX4(h0, h1, h2, h3, base + 2 * TSZ + nb);
                uint32_t bh0[2] = {h0, h1}, bh1[2] = {h2, h3};
                #pragma unroll
                for (int i = 0; i < 4; i++) {
                    mma16816f(acc[i][2*p],   ah[i], bh0);
                    mma16816f(acc[i][2*p+1], ah[i], bh1);
                    mma16816f(acc[i][2*p],   al[i], bh0);
                    mma16816f(acc[i][2*p+1], al[i], bh1);
                }
            }
        }
        __syncthreads();
    }

    // ---- epilogue: regs -> Osm ----
    float* Osm = (float*)smem;
    #pragma unroll
    for (int i = 0; i < 4; i++) {
        int r0 = warpm * 64 + i * 16 + lrw;
        #pragma unroll
        for (int j = 0; j < 4; j++) {
            int c0 = warpn * 32 + j * 8 + lk * 2;
            Osm[r0 * 132 + c0]           = acc[i][j][0];
            Osm[r0 * 132 + c0 + 1]       = acc[i][j][1];
            Osm[(r0 + 8) * 132 + c0]     = acc[i][j][2];
            Osm[(r0 + 8) * 132 + c0 + 1] = acc[i][j][3];
        }
    }
    __syncthreads();

    int h = (n0 >> 7) & 15;
    if (mode == 3) {
        #pragma unroll
        for (int it = 0; it < 16; it++) {
            int f = it * 256 + tid;
            int r = f >> 5, c4 = (f & 31) << 2;
            float4 v = *(float4*)&Osm[r * 132 + c4];
            *(float4*)&Dout[(size_t)(m0 + r) * HIDDEN + n0 + c4] = v;
        }
    } else if (mode == 2) {
        // v: transpose -> single fp16 plane [bh][d][s]
        #pragma unroll
        for (int it = 0; it < 64; it++) {
            int f = it * 256 + tid;
            int mloc = f & 127, d = (f >> 7) & 127;
            float val = Osm[mloc * 132 + d];
            int m = m0 + mloc;
            int b = m >> 11, s = m & (SEQ - 1);
            g_vf[((size_t)((b * HEADS + h) * HD + d)) * SEQ + s] = __float2half_rn(val);
        }
    } else if (mode == 0) {
        // q: rope + scale -> fp16 hi/lo [bh][s][hi128|lo128]
        const float scale = 0.08838834764831845f;
        #pragma unroll
        for (int it = 0; it < 32; it++) {
            int f = it * 256 + tid;
            int r = f >> 6, i = f & 63;
            int m = m0 + r;
            int b = m >> 11, s = m & (SEQ - 1);
            float x1 = Osm[r * 132 + i], x2 = Osm[r * 132 + i + 64];
            float c = g_cos[s * 64 + i], sn = g_sin[s * 64 + i];
            float o1 = (x1 * c - x2 * sn) * scale;
            float o2 = (x2 * c + x1 * sn) * scale;
            __half h1 = __float2half_rn(o1), h2 = __float2half_rn(o2);
            __half l1 = __float2half_rn(o1 - __half2float(h1));
            __half l2 = __float2half_rn(o2 - __half2float(h2));
            size_t base = ((size_t)(b * HEADS + h) * SEQ + s) * 256;
            g_qp[base + i] = h1; g_qp[base + i + 64] = h2;
            g_qp[base + 128 + i] = l1; g_qp[base + 128 + i + 64] = l2;
        }
    } else {
        // k: rope -> single fp16 plane [bh][s][128]
        #pragma unroll
        for (int it = 0; it < 32; it++) {
            int f = it * 256 + tid;
            int r = f >> 6, i = f & 63;
            int m = m0 + r;
            int b = m >> 11, s = m & (SEQ - 1);
            float x1 = Osm[r * 132 + i], x2 = Osm[r * 132 + i + 64];
            float c = g_cos[s * 64 + i], sn = g_sin[s * 64 + i];
            size_t base = ((size_t)(b * HEADS + h) * SEQ + s) * 128;
            g_kp[base + i]      = __float2half_rn(x1 * c - x2 * sn);
            g_kp[base + i + 64] = __float2half_rn(x2 * c + x1 * sn);
        }
    }
}

// ------------- flash attention: S = (Qh+Ql)*K 2-pass; PV = (Phi+Plo)*V 2-pass ---
#define AQ_STR 528
#define AK_STR 272
#define AV_STR 144
#define AOFF_K (128*AQ_STR)          // 67584
#define AK_SZ  (64*AK_STR)           // 17408
#define AOFF_V (AOFF_K + 2*AK_SZ)    // 102400
#define AV_SZ  (128*AV_STR)          // 18432
#define ATTN_SMEM (AOFF_V + 2*AV_SZ) // 139264
#define NEGB   -1e30f

__global__ __launch_bounds__(256, 1)
void attn_kernel()
{
    extern __shared__ char sm[];
    uint32_t sb = smem_u32(sm);
    int tid = threadIdx.x, wid = tid >> 5, lane = tid & 31;
    int lrw = lane >> 2, lk = lane & 3;
    int qt = 15 - (blockIdx.x >> 5);     // heavy-first
    int bh = blockIdx.x & 31;

    // Q tile: 128 rows x 512B
    {
        int r = tid >> 1, c0 = (tid & 1) * 256;
        uint32_t s = sb + r * AQ_STR + c0;
        const char* g = (const char*)g_qp + ((size_t)bh * SEQ + (size_t)qt * 128 + r) * 512 + c0;
        #pragma unroll
        for (int j = 0; j < 16; j++) cp_async16cg(s + j * 16, g + j * 16);
        CP_COMMIT();
    }
    int kr = tid >> 2, kc = (tid & 3) * 64;   // K: 64 rows x 256B
    int vr = tid >> 1, vc = (tid & 1) * 64;   // V: 128 rows x 128B
    auto issue_kv = [&](int kt, int buf) {
        uint32_t s = sb + AOFF_K + buf * AK_SZ + kr * AK_STR + kc;
        const char* g = (const char*)g_kp + ((size_t)bh * SEQ + (size_t)kt * 64 + kr) * 256 + kc;
        #pragma unroll
        for (int j = 0; j < 4; j++) cp_async16cg(s + j * 16, g + j * 16);
        uint32_t sv = sb + AOFF_V + buf * AV_SZ + vr * AV_STR + vc;
        const char* vg = (const char*)(g_vf + ((size_t)bh * HD + vr) * SEQ + (size_t)kt * 64) + vc;
        #pragma unroll
        for (int j = 0; j < 4; j++) cp_async16cg(sv + j * 16, vg + j * 16);
        CP_COMMIT();
    };

    issue_kv(0, 0);

    float accO[16][4];
    #pragma unroll
    for (int nt = 0; nt < 16; nt++)
        #pragma unroll
        for (int r = 0; r < 4; r++) accO[nt][r] = 0.f;
    float mA = NEGB, mB = NEGB, lA = 0.f, lB = 0.f;

    uint32_t qfb = sb + (wid * 16 + (lane & 15)) * AQ_STR + ((lane >> 4) << 4);
    uint32_t kfo = (uint32_t)(((lane & 7) + ((lane >> 4) << 3)) * AK_STR + (((lane >> 3) & 1) << 4));
    uint32_t vfo = (uint32_t)(((lane & 7) + ((lane >> 4) << 3)) * AV_STR + (((lane >> 3) & 1) << 4));
    int rgA = qt * 128 + wid * 16 + lrw;
    int nkt = 2 * qt + 2;

    CP_WAIT(1);
    __syncthreads();
    uint32_t qhi[8][4], qlo[8][4];
    #pragma unroll
    for (int ks = 0; ks < 8; ks++) {
        LDMX4(qhi[ks][0], qhi[ks][1], qhi[ks][2], qhi[ks][3], qfb + ks * 32);
        LDMX4(qlo[ks][0], qlo[ks][1], qlo[ks][2], qlo[ks][3], qfb + 256 + ks * 32);
    }

    for (int kt = 0; kt < nkt; kt++) {
        if (kt + 1 < nkt) { issue_kv(kt + 1, (kt + 1) & 1); CP_WAIT(1); }
        else              { CP_WAIT(0); }
        __syncthreads();

        if (kt * 64 <= qt * 128 + wid * 16 + 15) {
            float sacc[8][4];
            #pragma unroll
            for (int nt = 0; nt < 8; nt++)
                #pragma unroll
                for (int r = 0; r < 4; r++) sacc[nt][r] = 0.f;

            uint32_t kbuf = sb + AOFF_K + (kt & 1) * AK_SZ + kfo;
            #pragma unroll
            for (int ks = 0; ks < 8; ks++) {
                #pragma unroll
                for (int np = 0; np < 4; np++) {
                    uint32_t k0, k1, k2, k3;
                    LDMX4(k0, k1, k2, k3, kbuf + np * 16 * AK_STR + ks * 32);
                    uint32_t kb0[2] = {k0, k1}, kb1[2] = {k2, k3};
                    mma16816f(sacc[2*np],   qhi[ks], kb0);
                    mma16816f(sacc[2*np+1], qhi[ks], kb1);
                    mma16816f(sacc[2*np],   qlo[ks], kb0);
                    mma16816f(sacc[2*np+1], qlo[ks], kb1);
                }
            }
            if (kt * 64 + 63 > qt * 128 + wid * 16) {
                #pragma unroll
                for (int nt = 0; nt < 8; nt++) {
                    int cg = kt * 64 + nt * 8 + 2 * lk;
                    if (cg     > rgA)     sacc[nt][0] = NEGB;
                    if (cg + 1 > rgA)     sacc[nt][1] = NEGB;
                    if (cg     > rgA + 8) sacc[nt][2] = NEGB;
                    if (cg + 1 > rgA + 8) sacc[nt][3] = NEGB;
                }
            }
            float nmA = mA, nmB = mB;
            #pragma unroll
            for (int nt = 0; nt < 8; nt++) {
                nmA = fmaxf(nmA, fmaxf(sacc[nt][0], sacc[nt][1]));
                nmB = fmaxf(nmB, fmaxf(sacc[nt][2], sacc[nt][3]));
            }
            nmA = fmaxf(nmA, __shfl_xor_sync(~0u, nmA, 1));
            nmA = fmaxf(nmA, __shfl_xor_sync(~0u, nmA, 2));
            nmB = fmaxf(nmB, __shfl_xor_sync(~0u, nmB, 1));
            nmB = fmaxf(nmB, __shfl_xor_sync(~0u, nmB, 2));
            float coA = __expf(mA - nmA), coB = __expf(mB - nmB);
            mA = nmA; mB = nmB;
            float sumA = 0.f, sumB = 0.f;
            #pragma unroll
            for (int nt = 0; nt < 8; nt++) {
                sacc[nt][0] = __expf(sacc[nt][0] - nmA);
                sacc[nt][1] = __expf(sacc[nt][1] - nmA);
                sacc[nt][2] = __expf(sacc[nt][2] - nmB);
                sacc[nt][3] = __expf(sacc[nt][3] - nmB);
                sumA += sacc[nt][0] + sacc[nt][1];
                sumB += sacc[nt][2] + sacc[nt][3];
            }
            sumA += __shfl_xor_sync(~0u, sumA, 1);
            sumA += __shfl_xor_sync(~0u, sumA, 2);
            sumB += __shfl_xor_sync(~0u, sumB, 1);
            sumB += __shfl_xor_sync(~0u, sumB, 2);
            lA = lA * coA + sumA;
            lB = lB * coB + sumB;
            #pragma unroll
            for (int nt = 0; nt < 16; nt++) {
                accO[nt][0] *= coA; accO[nt][1] *= coA;
                accO[nt][2] *= coB; accO[nt][3] *= coB;
            }
            // P -> fp16 hi/lo fragments
            uint32_t phi[4][4], plo[4][4];
            #pragma unroll
            for (int s = 0; s < 4; s++) {
                #pragma unroll
                for (int half = 0; half < 2; half++) {
                    int nt = 2 * s + half;
                    float p0 = sacc[nt][0], p1 = sacc[nt][1];
                    float p2 = sacc[nt][2], p3 = sacc[nt][3];
                    PACK_F16(phi[s][2*half],   p0, p1);
                    PACK_F16(phi[s][2*half+1], p2, p3);
                    float r0 = p0 - __half2float(__float2half_rn(p0));
                    float r1 = p1 - __half2float(__float2half_rn(p1));
                    float r2 = p2 - __half2float(__float2half_rn(p2));
                    float r3 = p3 - __half2float(__float2half_rn(p3));
                    PACK_F16(plo[s][2*half],   r0, r1);
                    PACK_F16(plo[s][2*half+1], r2, r3);
                }
            }
            // PV: 2-pass on single V plane
            uint32_t vbuf = sb + AOFF_V + (kt & 1) * AV_SZ + vfo;
            #pragma unroll
            for (int ks = 0; ks < 4; ks++) {
                #pragma unroll
                for (int nt16 = 0; nt16 < 8; nt16++) {
                    uint32_t v0, v1, v2, v3;
                    LDMX4(v0, v1, v2, v3, vbuf + nt16 * 16 * AV_STR + ks * 32);
                    uint32_t vb0[2] = {v0, v1}, vb1[2] = {v2, v3};
                    mma16816f(accO[2*nt16],   phi[ks], vb0);
                    mma16816f(accO[2*nt16+1], phi[ks], vb1);
                    mma16816f(accO[2*nt16],   plo[ks], vb0);
                    mma16816f(accO[2*nt16+1], plo[ks], vb1);
                }
            }
        }
        __syncthreads();
    }

    float iA = 1.f / lA, iB = 1.f / lB;
    float* Osm = (float*)sm;
    int r0 = wid * 16 + lrw;
    #pragma unroll
    for (int nt = 0; nt < 16; nt++) {
        int c = nt * 8 + 2 * lk;
        *(float2*)&Osm[r0 * 132 + c]       = make_float2(accO[nt][0] * iA, accO[nt][1] * iA);
        *(float2*)&Osm[(r0 + 8) * 132 + c] = make_float2(accO[nt][2] * iB, accO[nt][3] * iB);
    }
    __syncthreads();
    // ctx -> fp16 hi/lo planes (exact-A for wo 2-pass)
    int bb = bh >> 4, h = bh & 15;
    #pragma unroll
    for (int it = 0; it < 32; it++) {
        int f = it * 256 + tid;
        int r = f >> 6, d2 = (f & 63) * 2;
        float v0 = Osm[r * 132 + d2], v1 = Osm[r * 132 + d2 + 1];
        __half h0 = __float2half_rn(v0), h1 = __float2half_rn(v1);
        __half e0 = __float2half_rn(v0 - __half2float(h0));
        __half e1 = __float2half_rn(v1 - __half2float(h1));
        uint32_t hp = (uint32_t)__half_as_ushort(h0) | ((uint32_t)__half_as_ushort(h1) << 16);
        uint32_t lp = (uint32_t)__half_as_ushort(e0) | ((uint32_t)__half_as_ushort(e1) << 16);
        size_t row = (size_t)bb * SEQ + (size_t)qt * 128 + r;
        size_t off = row * HIDDEN + h * 128 + d2;
        *(uint32_t*)(g_Ch + off) = hp;
        *(uint32_t*)(g_Cl + off) = lp;
    }
}

// ------------- launcher ---------------------------------------------------------
extern "C" void kernel_launch(void* const* d_in, const int* in_sizes, int n_in,
                              void* d_out, int out_size)
{
    (void)in_sizes; (void)n_in; (void)out_size;
    const float* X  = (const float*)d_in[0];
    const float* wq = (const float*)d_in[1];
    const float* wk = (const float*)d_in[2];
    const float* wv = (const float*)d_in[3];
    const float* wo = (const float*)d_in[4];
    float* out = (float*)d_out;

    __half *afh, *afl, *wf, *ch, *cl;
    cudaGetSymbolAddress((void**)&afh, g_Afh);
    cudaGetSymbolAddress((void**)&afl, g_Afl);
    cudaGetSymbolAddress((void**)&wf,  g_Wf);
    cudaGetSymbolAddress((void**)&ch,  g_Ch);
    cudaGetSymbolAddress((void**)&cl,  g_Cl);

    cudaFuncSetAttribute(gemmf, cudaFuncAttributeMaxDynamicSharedMemorySize, G_SMEM_BYTES);
    cudaFuncSetAttribute(attn_kernel, cudaFuncAttributeMaxDynamicSharedMemorySize, ATTN_SMEM);

    rope_table_kernel<<<(SEQ * 64 + 255) / 256, 256>>>();

    convert_x<<<(MTOT * HIDDEN / 4 + 255) / 256, 256>>>(X);
    convert_w4<<<(4 * HIDDEN * (HIDDEN / 4) + 255) / 256, 256>>>(wq, wk, wv, wo);

    // fused q/k/v projections (which = x>>4)
    gemmf<<<dim3(48, 32), 256, G_SMEM_BYTES>>>(afh, afl, wf, out, 1);

    attn_kernel<<<512, 256, ATTN_SMEM>>>();

    // output projection
    gemmf<<<dim3(16, 32), 256, G_SMEM_BYTES>>>(ch, cl,
        wf + (size_t)3 * HIDDEN * HIDDEN, out, 0);
}